// round 4
// baseline (speedup 1.0000x reference)
#include <cuda_runtime.h>

// h_t = alpha_t * h_{t-1} + x_t over axis 1 of float32 [4, 8192, 1024].
// Single-pass scan, decoupled lookback with two-state (aggregate/inclusive)
// flags and early-exit backward fold. float4-vectorized memory path.

#define B_      4
#define S_      8192
#define D_      1024
#define R_      4                     // s-steps per thread
#define SUBS_   16                    // s-subchunks (warps) per block
#define TPB_    512
#define DTILE_  128                   // d per block: 32 threads x float4
#define NDT_    (D_ / DTILE_)         // 8 d-tiles
#define SCHUNK_ (R_ * SUBS_)          // 64 s-steps per block/level
#define LEVELS_ (S_ / SCHUNK_)        // 128 levels per chain
#define LG_     (B_ * NDT_)           // 32 chains

// Lookback scratch (device globals). Rows of 32 float4 = 512B, coalesced.
__device__ float4 g_aggP[LG_][LEVELS_][32];
__device__ float4 g_aggL[LG_][LEVELS_][32];
__device__ float4 g_incl[LG_][LEVELS_][32];
__device__ int    g_flags[LG_][LEVELS_];

__global__ void zero_flags_kernel() {
    int i = blockIdx.x * blockDim.x + threadIdx.x;
    if (i < LG_ * LEVELS_) ((int*)g_flags)[i] = 0;
}

static __device__ __forceinline__ float4 fma4(float4 a, float4 b, float4 c) {
    float4 r;
    r.x = fmaf(a.x, b.x, c.x); r.y = fmaf(a.y, b.y, c.y);
    r.z = fmaf(a.z, b.z, c.z); r.w = fmaf(a.w, b.w, c.w);
    return r;
}
static __device__ __forceinline__ float4 mul4(float4 a, float4 b) {
    return make_float4(a.x * b.x, a.y * b.y, a.z * b.z, a.w * b.w);
}

__global__ __launch_bounds__(TPB_, 2) void scan_kernel(const float* __restrict__ x,
                                                       const float* __restrict__ alpha,
                                                       float* __restrict__ out) {
    __shared__ float4 sp[SUBS_][32];   // per-subchunk cumprod(alpha)
    __shared__ float4 sl[SUBS_][32];   // per-subchunk local scan value
    __shared__ float4 s_cin[32];       // carry-in for this block

    const int tid   = threadIdx.x;
    const int lane  = tid & 31;
    const int w     = tid >> 5;           // s-subchunk index
    const int lg    = blockIdx.x;         // chain: b * NDT_ + dtile
    const int level = blockIdx.y;
    const int b     = lg >> 3;
    const int dt    = lg & 7;
    const int d     = dt * DTILE_ + lane * 4;
    const int s0    = level * SCHUNK_ + w * R_;
    const size_t base = ((size_t)b * S_ + s0) * (size_t)D_ + d;

    // ---- Phase 1: local scan in registers ----
    float4 A[R_], X[R_];
#pragma unroll
    for (int r = 0; r < R_; r++)
        A[r] = __ldcs((const float4*)(alpha + base + (size_t)r * D_));
#pragma unroll
    for (int r = 0; r < R_; r++)
        X[r] = __ldcs((const float4*)(x + base + (size_t)r * D_));

    float4 P = make_float4(1.f, 1.f, 1.f, 1.f);
    float4 L = make_float4(0.f, 0.f, 0.f, 0.f);
#pragma unroll
    for (int r = 0; r < R_; r++) {
        L = fma4(A[r], L, X[r]);
        P = mul4(P, A[r]);
        A[r] = P;
        X[r] = L;
    }
    sp[w][lane] = P;
    sl[w][lane] = L;
    __syncthreads();

    // ---- Phase 2 (warp 0): publish aggregate, backward lookback, publish inclusive ----
    if (w == 0) {
        float4 Pb = make_float4(1.f, 1.f, 1.f, 1.f);
        float4 Lb = make_float4(0.f, 0.f, 0.f, 0.f);
#pragma unroll
        for (int w2 = 0; w2 < SUBS_; w2++) {
            Lb = fma4(sp[w2][lane], Lb, sl[w2][lane]);
            Pb = mul4(Pb, sp[w2][lane]);
        }
        __stcg(&g_aggP[lg][level][lane], Pb);
        __stcg(&g_aggL[lg][level][lane], Lb);
        __threadfence();
        __syncwarp();
        if (lane == 0) atomicExch(&g_flags[lg][level], 1);

        // Backward lookback with early exit at first inclusive predecessor.
        // Invariant: cin = accA * H(j) + accB  (H = inclusive carry of level j)
        float4 cin = make_float4(0.f, 0.f, 0.f, 0.f);
        if (level > 0) {
            float4 accA = make_float4(1.f, 1.f, 1.f, 1.f);
            float4 accB = make_float4(0.f, 0.f, 0.f, 0.f);
            volatile int* fl = &g_flags[lg][0];
            int j = level - 1;
            while (j >= 0) {
                int f = 0;
                if (lane == 0) { do { f = fl[j]; } while (f == 0); }
                f = __shfl_sync(0xffffffffu, f, 0);
                __threadfence();
                if (f == 2) {
                    float4 I = __ldcg(&g_incl[lg][j][lane]);
                    accB = fma4(accA, I, accB);
                    break;
                } else {
                    float4 p = __ldcg(&g_aggP[lg][j][lane]);
                    float4 l = __ldcg(&g_aggL[lg][j][lane]);
                    accB = fma4(accA, l, accB);
                    accA = mul4(accA, p);
                    j--;
                }
            }
            cin = accB;
        }
        // Publish inclusive carry for this level: H = Pb * cin + Lb
        __stcg(&g_incl[lg][level][lane], fma4(Pb, cin, Lb));
        __threadfence();
        __syncwarp();
        if (lane == 0) atomicExch(&g_flags[lg][level], 2);

        s_cin[lane] = cin;
    }
    __syncthreads();

    // ---- Phase 3: apply carry prefix, write output ----
    float4 h0 = s_cin[lane];
    for (int w2 = 0; w2 < w; w2++)
        h0 = fma4(sp[w2][lane], h0, sl[w2][lane]);

#pragma unroll
    for (int r = 0; r < R_; r++) {
        float4 o = fma4(A[r], h0, X[r]);
        __stcs((float4*)(out + base + (size_t)r * D_), o);
    }
}

extern "C" void kernel_launch(void* const* d_in, const int* in_sizes, int n_in,
                              void* d_out, int out_size) {
    const float* xp = (const float*)d_in[0];
    const float* ap = (const float*)d_in[1];
    float* op = (float*)d_out;

    zero_flags_kernel<<<(LG_ * LEVELS_ + 255) / 256, 256>>>();
    scan_kernel<<<dim3(LG_, LEVELS_), TPB_>>>(xp, ap, op);
}

// round 5
// speedup vs baseline: 1.1037x; 1.1037x over previous
#include <cuda_runtime.h>

// h_t = alpha_t * h_{t-1} + x_t over axis 1 of float32 [4, 8192, 1024].
// Single-pass decoupled-lookback scan. A dedicated scan warp (warp 16) folds
// predecessor aggregates concurrently with the data warps' Phase-1 streaming;
// handoff via named arrive/sync barriers so data warps never idle on L2.

#define B_      4
#define S_      8192
#define D_      1024
#define R_      16                    // s-steps per data thread
#define SUBS_   16                    // data warps per block
#define TPB_    544                   // 16 data warps + 1 scan warp
#define DATA_T_ 512
#define DTILE_  32                    // d-lanes per block
#define SCHUNK_ (R_ * SUBS_)          // 256 s-steps per block/level
#define LEVELS_ (S_ / SCHUNK_)        // 32 levels per chain
#define LG_     (B_ * (D_ / DTILE_))  // 128 chains

// Aggregate scratch (device globals). Lane-contiguous 128B rows.
__device__ float g_aggP[LG_][LEVELS_][DTILE_];
__device__ float g_aggL[LG_][LEVELS_][DTILE_];
__device__ int   g_flags[LG_][LEVELS_];

__global__ void zero_flags_kernel() {
    int i = blockIdx.x * blockDim.x + threadIdx.x;
    if (i < LG_ * LEVELS_) ((int*)g_flags)[i] = 0;
}

__global__ __launch_bounds__(TPB_, 2) void scan_kernel(const float* __restrict__ x,
                                                       const float* __restrict__ alpha,
                                                       float* __restrict__ out) {
    __shared__ float sp[SUBS_][DTILE_];   // per-subchunk cumprod(alpha)
    __shared__ float sl[SUBS_][DTILE_];   // per-subchunk local scan value
    __shared__ float s_cin[DTILE_];       // carry-in for this block

    const int tid   = threadIdx.x;
    const int lane  = tid & 31;
    const int w     = tid >> 5;           // 0..15 data, 16 scan
    const int lg    = blockIdx.x;         // chain: b * 32 + dtile
    const int level = blockIdx.y;
    const int b     = lg >> 5;
    const int dt    = lg & 31;

    if (w == SUBS_) {
        // ================= scan warp =================
        // 1) Fold predecessor aggregates (overlapped with data warps' Phase 1).
        float cin = 0.0f;
        if (level > 0) {
            volatile int* fl = &g_flags[lg][0];
            const bool need = (lane < level);
            while (__any_sync(0xffffffffu, need && (fl[lane] == 0))) { /* spin */ }
            __threadfence();
            int j = 0;
            while (j < level) {
                const int t = level - j;
                float p0[4], l0[4];
#pragma unroll
                for (int k = 0; k < 4; k++) {
                    if (k < t) {
                        p0[k] = __ldcg(&g_aggP[lg][j + k][lane]);
                        l0[k] = __ldcg(&g_aggL[lg][j + k][lane]);
                    }
                }
#pragma unroll
                for (int k = 0; k < 4; k++)
                    if (k < t) cin = fmaf(p0[k], cin, l0[k]);
                j += 4;
            }
        }

        // 2) Wait for data warps' smem aggregates.
        asm volatile("bar.sync 1, %0;" :: "n"(TPB_) : "memory");

        // 3) Block aggregate + publish.
        float Pb = 1.0f, Lb = 0.0f;
#pragma unroll
        for (int w2 = 0; w2 < SUBS_; w2++) {
            Lb = fmaf(sp[w2][lane], Lb, sl[w2][lane]);
            Pb = Pb * sp[w2][lane];
        }
        __stcg(&g_aggP[lg][level][lane], Pb);
        __stcg(&g_aggL[lg][level][lane], Lb);
        __threadfence();
        __syncwarp();
        if (lane == 0) atomicExch(&g_flags[lg][level], 1);

        // 4) Hand carry to data warps.
        s_cin[lane] = cin;
        asm volatile("bar.arrive 2, %0;" :: "n"(TPB_) : "memory");
    } else {
        // ================= data warps =================
        const int d  = dt * DTILE_ + lane;
        const int s0 = level * SCHUNK_ + w * R_;
        const size_t base = ((size_t)b * S_ + s0) * (size_t)D_ + d;

        float A[R_], X[R_];
#pragma unroll
        for (int r = 0; r < R_; r++) A[r] = __ldcs(alpha + base + (size_t)r * D_);
#pragma unroll
        for (int r = 0; r < R_; r++) X[r] = __ldcs(x + base + (size_t)r * D_);

        float P = 1.0f, L = 0.0f;
#pragma unroll
        for (int r = 0; r < R_; r++) {
            L = fmaf(A[r], L, X[r]);
            P = P * A[r];
            A[r] = P;   // per-step cumprod
            X[r] = L;   // per-step local scan
        }
        sp[w][lane] = P;
        sl[w][lane] = L;
        asm volatile("bar.arrive 1, %0;" :: "n"(TPB_) : "memory");

        // Wait for carry from scan warp.
        asm volatile("bar.sync 2, %0;" :: "n"(TPB_) : "memory");

        float h0 = s_cin[lane];
        for (int w2 = 0; w2 < w; w2++)
            h0 = fmaf(sp[w2][lane], h0, sl[w2][lane]);

#pragma unroll
        for (int r = 0; r < R_; r++)
            __stcs(out + base + (size_t)r * D_, fmaf(A[r], h0, X[r]));
    }
}

extern "C" void kernel_launch(void* const* d_in, const int* in_sizes, int n_in,
                              void* d_out, int out_size) {
    const float* xp = (const float*)d_in[0];
    const float* ap = (const float*)d_in[1];
    float* op = (float*)d_out;

    zero_flags_kernel<<<(LG_ * LEVELS_ + 255) / 256, 256>>>();
    scan_kernel<<<dim3(LG_, LEVELS_), TPB_>>>(xp, ap, op);
}

// round 6
// speedup vs baseline: 1.6856x; 1.5271x over previous
#include <cuda_runtime.h>

// h_t = alpha_t * h_{t-1} + x_t over axis 1 of float32 [4, 8192, 1024].
// Persistent design: one block per (batch, 32-wide d-tile) chain = 128 blocks.
// Each block scans its full S=8192 sequence in 32 chunks of 256 steps with
// register double-buffered prefetch. Carry is block-local: no flags, no
// atomics, no fences, no launch waves. One __syncthreads per chunk.

#define B_      4
#define S_      8192
#define D_      1024
#define R_      16                    // s-steps per thread per chunk
#define SUBS_   16                    // warps per block
#define TPB_    512
#define DTILE_  32                    // d-lanes per block
#define CHUNK_  (R_ * SUBS_)          // 256 s-steps per chunk
#define ITERS_  (S_ / CHUNK_)         // 32 chunks per chain
#define LG_     (B_ * (D_ / DTILE_))  // 128 chains = 128 blocks

// One chunk body. CUR/NXT are compile-time buffer indices (ping-pong).
// Order matters: prefetch LDGs for chunk K+1 are issued BEFORE the local
// scan / barrier / stores of chunk K, so DRAM streams across the sync.
#define BODY(CUR, NXT, K)                                                     \
    {                                                                         \
        const size_t nbase = base + (size_t)CHUNK_ * D_;                      \
        if ((K) + 1 < ITERS_) {                                               \
            _Pragma("unroll")                                                 \
            for (int r = 0; r < R_; r++)                                      \
                A[NXT][r] = __ldcs(alpha + nbase + (size_t)r * D_);           \
            _Pragma("unroll")                                                 \
            for (int r = 0; r < R_; r++)                                      \
                X[NXT][r] = __ldcs(x + nbase + (size_t)r * D_);               \
        }                                                                     \
        float P = 1.0f, L = 0.0f;                                             \
        _Pragma("unroll")                                                     \
        for (int r = 0; r < R_; r++) {                                        \
            L = fmaf(A[CUR][r], L, X[CUR][r]);                                \
            P = P * A[CUR][r];                                                \
            A[CUR][r] = P;   /* per-step cumprod  */                          \
            X[CUR][r] = L;   /* per-step local scan */                        \
        }                                                                     \
        sp[CUR][w][lane] = P;                                                 \
        sl[CUR][w][lane] = L;                                                 \
        __syncthreads();                                                      \
        /* every warp folds all 16 aggregates: h0 = prefix before own warp, */\
        /* acc = full fold -> next chunk's carry (identical in all warps).  */\
        float acc = cin, h0 = cin;                                            \
        _Pragma("unroll")                                                     \
        for (int w2 = 0; w2 < SUBS_; w2++) {                                  \
            if (w2 == w) h0 = acc;                                            \
            acc = fmaf(sp[CUR][w2][lane], acc, sl[CUR][w2][lane]);            \
        }                                                                     \
        cin = acc;                                                            \
        _Pragma("unroll")                                                     \
        for (int r = 0; r < R_; r++)                                          \
            __stcs(out + base + (size_t)r * D_, fmaf(A[CUR][r], h0, X[CUR][r]));\
        base = nbase;                                                         \
    }

__global__ __launch_bounds__(TPB_, 1) void scan_kernel(const float* __restrict__ x,
                                                       const float* __restrict__ alpha,
                                                       float* __restrict__ out) {
    // Double-buffered per-warp aggregates: one __syncthreads per chunk is
    // race-free (sync at k+1 separates read(k) from write(k+2), same buffer).
    __shared__ float sp[2][SUBS_][DTILE_];
    __shared__ float sl[2][SUBS_][DTILE_];

    const int lane = threadIdx.x & 31;
    const int w    = threadIdx.x >> 5;    // warp = s-subchunk within chunk
    const int lg   = blockIdx.x;          // chain: b * 32 + dtile
    const int b    = lg >> 5;
    const int dt   = lg & 31;
    const int d    = dt * DTILE_ + lane;

    size_t base = ((size_t)b * S_ + (size_t)w * R_) * (size_t)D_ + d;

    float A[2][R_], X[2][R_];
    float cin = 0.0f;

    // Preload chunk 0.
#pragma unroll
    for (int r = 0; r < R_; r++) A[0][r] = __ldcs(alpha + base + (size_t)r * D_);
#pragma unroll
    for (int r = 0; r < R_; r++) X[0][r] = __ldcs(x + base + (size_t)r * D_);

#pragma unroll 1
    for (int k = 0; k < ITERS_; k += 2) {
        BODY(0, 1, k)
        BODY(1, 0, k + 1)
    }
}

extern "C" void kernel_launch(void* const* d_in, const int* in_sizes, int n_in,
                              void* d_out, int out_size) {
    const float* xp = (const float*)d_in[0];
    const float* ap = (const float*)d_in[1];
    float* op = (float*)d_out;

    scan_kernel<<<LG_, TPB_>>>(xp, ap, op);
}